// round 5
// baseline (speedup 1.0000x reference)
#include <cuda_runtime.h>
#include <cuda_bf16.h>
#include <cstdint>

#define T_LEN 1024
#define B_N   128
#define H_N   256
#define G3    768

typedef unsigned long long u64;

// ---------------- scratch (device globals; no allocations allowed) ----------
__device__ float g_xg[(size_t)T_LEN * B_N * G3];      // [t][b][768]
__device__ float g_seq[(size_t)B_N * T_LEN * H_N];    // [b][t][256] layer-1 output
__device__ float g_hlast[B_N * H_N];                  // layer-2 final hidden

// ---------------- helpers ---------------------------------------------------
__device__ __forceinline__ float sigmoidf_(float x) {
    return __fdividef(1.0f, 1.0f + __expf(-x));
}
__device__ __forceinline__ float tanhf_(float x) {
    float ax = fabsf(x);
    float e  = __expf(-2.0f * ax);            // in (0,1], no overflow
    float t  = __fdividef(1.0f - e, 1.0f + e);
    return copysignf(t, x);
}

// packed fp32x2 FMA: d = a*b + d  (lanes independent, rn)
__device__ __forceinline__ void fma2_(u64& d, u64 a, u64 b) {
    asm("fma.rn.f32x2 %0, %1, %2, %0;" : "+l"(d) : "l"(a), "l"(b));
}
__device__ __forceinline__ void unpack2_(u64 v, float& lo, float& hi) {
    asm("mov.b64 {%0, %1}, %2;" : "=f"(lo), "=f"(hi) : "l"(v));
}
__device__ __forceinline__ float foldadd_(u64 v) {
    float lo, hi; unpack2_(v, lo, hi); return lo + hi;
}

__device__ __forceinline__ void cluster_arrive_() {
    asm volatile("barrier.cluster.arrive.aligned;" ::: "memory");
}
__device__ __forceinline__ void cluster_wait_() {
    asm volatile("barrier.cluster.wait.aligned;" ::: "memory");
}
__device__ __forceinline__ void st_shared_cluster_f32(uint32_t laddr, uint32_t rank, float v) {
    uint32_t raddr;
    asm volatile("mapa.shared::cluster.u32 %0, %1, %2;" : "=r"(raddr) : "r"(laddr), "r"(rank));
    asm volatile("st.shared::cluster.f32 [%0], %1;" :: "r"(raddr), "f"(v) : "memory");
}
__device__ __forceinline__ uint32_t smem_u32(const void* p) {
    return (uint32_t)__cvta_generic_to_shared(p);
}

// ============================================================================
// Input projection GEMM (unchanged from R3, K-packed fp32x2, natural layouts)
// ============================================================================
#define SA_ST 258
#define SB_ST 258
#define GEMM_SMEM ((128*SA_ST + 64*SB_ST) * 4)

__global__ void __launch_bounds__(256, 1) gemm_xg_kernel(
    const float* __restrict__ Ax,
    const float* __restrict__ W,
    const float* __restrict__ bias,
    int use_gseq)
{
    extern __shared__ float sm[];
    float* sA = sm;                    // [128 m][258]
    float* sB = sm + 128 * SA_ST;      // [64  n][258]

    const float* A = use_gseq ? g_seq : Ax;

    const int tid = threadIdx.x;
    const int t  = blockIdx.y;
    const int nt = blockIdx.x;

#pragma unroll
    for (int i = 0; i < 32; i++) {
        int lin = i * 256 + tid;
        int m   = lin >> 6;
        int k4  = (lin & 63) << 2;
        float4 v = *(const float4*)(A + ((size_t)m * T_LEN + t) * H_N + k4);
        float* d = sA + m * SA_ST + k4;
        *(float2*)(d)     = make_float2(v.x, v.y);
        *(float2*)(d + 2) = make_float2(v.z, v.w);
    }
#pragma unroll
    for (int i = 0; i < 16; i++) {
        int lin = i * 256 + tid;
        int n   = lin >> 6;
        int k4  = (lin & 63) << 2;
        float4 v = *(const float4*)(W + ((size_t)(nt * 64 + n)) * H_N + k4);
        float* d = sB + n * SB_ST + k4;
        *(float2*)(d)     = make_float2(v.x, v.y);
        *(float2*)(d + 2) = make_float2(v.z, v.w);
    }
    __syncthreads();

    const int tx = tid >> 4;   // 0..15 -> n = tx + 16i
    const int ty = tid & 15;   // 0..15 -> m = ty + 16j

    u64 acc[8][4];
#pragma unroll
    for (int j = 0; j < 8; j++)
#pragma unroll
        for (int i = 0; i < 4; i++) acc[j][i] = 0ull;

#pragma unroll 4
    for (int kq = 0; kq < 128; kq++) {
        u64 a[8], b[4];
#pragma unroll
        for (int j = 0; j < 8; j++)
            a[j] = *(const u64*)(sA + (ty + (j << 4)) * SA_ST + 2 * kq);
#pragma unroll
        for (int i = 0; i < 4; i++)
            b[i] = *(const u64*)(sB + (tx + (i << 4)) * SB_ST + 2 * kq);
#pragma unroll
        for (int j = 0; j < 8; j++)
#pragma unroll
            for (int i = 0; i < 4; i++) fma2_(acc[j][i], a[j], b[i]);
    }

#pragma unroll
    for (int i = 0; i < 4; i++) {
        int n  = nt * 64 + tx + (i << 4);
        float bv = bias[n];
#pragma unroll
        for (int j = 0; j < 8; j++) {
            int m = ty + (j << 4);
            float lo, hi;
            unpack2_(acc[j][i], lo, hi);
            g_xg[((size_t)t * B_N + m) * G3 + n] = lo + hi + bv;
        }
    }
}

// ============================================================================
// GRU recurrence v4: 4-CTA clusters, 384 threads.
// Thread = (rp = tid>>2 in [0,96), kq = tid&3): rows {2rp, 2rp+1}, k-quarter
// [kq*64, kq*64+64). First 32 k of the quarter in REGISTERS (wr0/wr1, 16 u64
// per row), last 32 k in SMEM transposed [pairidx][tid] (conflict-free LDS.64).
// k-reduction via shfl.xor over kq (lanes l^1, l^2 of the same warp), then
// 3KB float4 staging + one __syncthreads + elementwise by tid<256.
// ============================================================================
#define REC_SMEM ((16*384*8)*2 + 2*1024*4 + 2*192*16)

__global__ void __cluster_dims__(4, 1, 1) __launch_bounds__(384, 1)
gru_rec_kernel(const float* __restrict__ Whh,   // this layer's [768][256]
               const float* __restrict__ bhh,   // this layer's [768]
               int layer)
{
    extern __shared__ char smc[];
    u64*    sW0 = (u64*)smc;                    // [16][384] row0 smem k-pairs
    u64*    sW1 = sW0 + 16 * 384;               // [16][384] row1
    float*  sH  = (float*)(sW1 + 16 * 384);     // [2][4 b][256]
    float4* sP  = (float4*)(sH + 2 * 1024);     // [2][192 rows] (4 b each)

    const int tid  = threadIdx.x;               // 0..383
    const int rank = blockIdx.x & 3;
    const int b0   = (blockIdx.x >> 2) * 4;

    const int rp = tid >> 2;                    // 0..95
    const int kq = tid & 3;                     // 0..3
    const int r0 = 2 * rp, r1 = 2 * rp + 1;     // local rows
    const int jg0 = ((r0 >> 6) << 8) + (rank << 6) + (r0 & 63);
    const int jg1 = ((r1 >> 6) << 8) + (rank << 6) + (r1 & 63);
    const int kb  = kq << 6;

    // ---- weights: first 32 k of quarter -> regs; last 32 -> smem ----
    u64 wr0[16], wr1[16];
    {
        const float* p0 = Whh + (size_t)jg0 * H_N + kb;
        const float* p1 = Whh + (size_t)jg1 * H_N + kb;
#pragma unroll
        for (int j = 0; j < 16; j++) {
            wr0[j] = *(const u64*)(p0 + 2 * j);
            wr1[j] = *(const u64*)(p1 + 2 * j);
        }
#pragma unroll
        for (int j = 0; j < 16; j++) {
            sW0[j * 384 + tid] = *(const u64*)(p0 + 32 + 2 * j);
            sW1[j * 384 + tid] = *(const u64*)(p1 + 32 + 2 * j);
        }
    }
    // ---- zero h double buffer ----
    for (int i = tid; i < 2048; i += 384) sH[i] = 0.0f;

    // elementwise assignment (first 256 threads): one (u, b) each
    const int eu  = tid >> 2;                   // 0..63 (valid tid<256)
    const int eb  = tid & 3;
    const int eug = (rank << 6) + (eu & 63);
    float br_ = 0.f, bz_ = 0.f, bn_ = 0.f;
    if (tid < 256) {
        br_ = bhh[eug]; bz_ = bhh[256 + eug]; bn_ = bhh[512 + eug];
    }

    __syncthreads();
    cluster_arrive_();
    cluster_wait_();

    int p = 0;
    for (int t = 0; t < T_LEN; t++) {
        // ---- issue xg LDGs BEFORE the wait (latency overlaps barrier skew) --
        float xr = 0.f, xz = 0.f, xn = 0.f;
        if (tid < 256) {
            size_t xb = ((size_t)t * B_N + b0 + eb) * G3 + eug;
            xr = g_xg[xb]; xz = g_xg[xb + 256]; xn = g_xg[xb + 512];
        }
        if (t > 0) cluster_wait_();             // h[p] published by all peers

        // ---- FMA phase: rows {r0,r1} x 4 b x 64 k ----
        const float* hk = sH + p * 1024 + kb;   // + b*256 per batch
        u64 a00 = 0, a01 = 0, a02 = 0, a03 = 0; // row0, b0..3
        u64 a10 = 0, a11 = 0, a12 = 0, a13 = 0; // row1, b0..3
        // k-sub 0..31: weights from registers
#pragma unroll
        for (int jj = 0; jj < 8; jj++) {
            u64 w0A = wr0[2 * jj], w0B = wr0[2 * jj + 1];
            u64 w1A = wr1[2 * jj], w1B = wr1[2 * jj + 1];
            ulonglong2 h0 = *(const ulonglong2*)(hk + 4 * jj);
            fma2_(a00, w0A, h0.x); fma2_(a00, w0B, h0.y);
            fma2_(a10, w1A, h0.x); fma2_(a10, w1B, h0.y);
            ulonglong2 h1 = *(const ulonglong2*)(hk + 256 + 4 * jj);
            fma2_(a01, w0A, h1.x); fma2_(a01, w0B, h1.y);
            fma2_(a11, w1A, h1.x); fma2_(a11, w1B, h1.y);
            ulonglong2 h2 = *(const ulonglong2*)(hk + 512 + 4 * jj);
            fma2_(a02, w0A, h2.x); fma2_(a02, w0B, h2.y);
            fma2_(a12, w1A, h2.x); fma2_(a12, w1B, h2.y);
            ulonglong2 h3 = *(const ulonglong2*)(hk + 768 + 4 * jj);
            fma2_(a03, w0A, h3.x); fma2_(a03, w0B, h3.y);
            fma2_(a13, w1A, h3.x); fma2_(a13, w1B, h3.y);
        }
        // k-sub 32..63: weights from smem (transposed, conflict-free)
#pragma unroll
        for (int jj = 0; jj < 8; jj++) {
            u64 w0A = sW0[(2 * jj) * 384 + tid], w0B = sW0[(2 * jj + 1) * 384 + tid];
            u64 w1A = sW1[(2 * jj) * 384 + tid], w1B = sW1[(2 * jj + 1) * 384 + tid];
            ulonglong2 h0 = *(const ulonglong2*)(hk + 32 + 4 * jj);
            fma2_(a00, w0A, h0.x); fma2_(a00, w0B, h0.y);
            fma2_(a10, w1A, h0.x); fma2_(a10, w1B, h0.y);
            ulonglong2 h1 = *(const ulonglong2*)(hk + 288 + 4 * jj);
            fma2_(a01, w0A, h1.x); fma2_(a01, w0B, h1.y);
            fma2_(a11, w1A, h1.x); fma2_(a11, w1B, h1.y);
            ulonglong2 h2 = *(const ulonglong2*)(hk + 544 + 4 * jj);
            fma2_(a02, w0A, h2.x); fma2_(a02, w0B, h2.y);
            fma2_(a12, w1A, h2.x); fma2_(a12, w1B, h2.y);
            ulonglong2 h3 = *(const ulonglong2*)(hk + 800 + 4 * jj);
            fma2_(a03, w0A, h3.x); fma2_(a03, w0B, h3.y);
            fma2_(a13, w1A, h3.x); fma2_(a13, w1B, h3.y);
        }

        // ---- fold pairs, shuffle-reduce over kq (lanes l^1, l^2) ----
        float s00 = foldadd_(a00), s01 = foldadd_(a01),
              s02 = foldadd_(a02), s03 = foldadd_(a03);
        float s10 = foldadd_(a10), s11 = foldadd_(a11),
              s12 = foldadd_(a12), s13 = foldadd_(a13);
#pragma unroll
        for (int d = 1; d < 4; d <<= 1) {
            s00 += __shfl_xor_sync(0xffffffffu, s00, d);
            s01 += __shfl_xor_sync(0xffffffffu, s01, d);
            s02 += __shfl_xor_sync(0xffffffffu, s02, d);
            s03 += __shfl_xor_sync(0xffffffffu, s03, d);
            s10 += __shfl_xor_sync(0xffffffffu, s10, d);
            s11 += __shfl_xor_sync(0xffffffffu, s11, d);
            s12 += __shfl_xor_sync(0xffffffffu, s12, d);
            s13 += __shfl_xor_sync(0xffffffffu, s13, d);
        }
        if (kq == 0) {
            sP[p * 192 + r0] = make_float4(s00, s01, s02, s03);
            sP[p * 192 + r1] = make_float4(s10, s11, s12, s13);
        }
        __syncthreads();

        // ---- elementwise (first 256 threads) ----
        float hnew = 0.f;
        if (tid < 256) {
            const float* pf = (const float*)(sP + p * 192);
            float hr = pf[(      eu) * 4 + eb] + br_;
            float hz = pf[( 64 + eu) * 4 + eb] + bz_;
            float hn = pf[(128 + eu) * 4 + eb] + bn_;

            float hold = sH[p * 1024 + eb * 256 + eug];
            float r = sigmoidf_(xr + hr);
            float z = sigmoidf_(xz + hz);
            float n = tanhf_(xn + r * hn);
            hnew = (1.0f - z) * n + z * hold;

            // broadcast to all 4 cluster CTAs (incl. self)
            uint32_t la = smem_u32(sH + (1 - p) * 1024 + eb * 256 + eug);
#pragma unroll
            for (uint32_t rr = 0; rr < 4; rr++)
                st_shared_cluster_f32(la, rr, hnew);
        }

        cluster_arrive_();   // release: publishes DSMEM h stores + frees sH[p]/sP[p]

        // global stores off the critical path
        if (tid < 256) {
            if (layer == 0) {
                g_seq[((size_t)(b0 + eb) * T_LEN + t) * H_N + eug] = hnew;
            } else if (t == T_LEN - 1) {
                g_hlast[(b0 + eb) * H_N + eug] = hnew;
            }
        }
        p ^= 1;
    }
    cluster_wait_();   // don't exit while peers' DSMEM stores may be in flight
}

// ============================================================================
// Final FC: out[b][n] = sigmoid(dot(g_hlast[b], W_fc[n]) + b_fc[n])
// ============================================================================
__global__ void fc_kernel(const float* __restrict__ Wfc,
                          const float* __restrict__ bfc,
                          float* __restrict__ out)
{
    __shared__ float sh[H_N];
    const int b = blockIdx.x, n = threadIdx.x;
    sh[n] = g_hlast[b * H_N + n];
    __syncthreads();
    const float* w = Wfc + (size_t)n * H_N;
    float acc = 0.0f;
#pragma unroll 4
    for (int k = 0; k < H_N; k++) acc += sh[k] * w[k];
    out[b * H_N + n] = sigmoidf_(acc + bfc[n]);
}

// ============================================================================
extern "C" void kernel_launch(void* const* d_in, const int* in_sizes, int n_in,
                              void* d_out, int out_size)
{
    const float* x   = (const float*)d_in[0];
    const float* Wih = (const float*)d_in[1];
    const float* Whh = (const float*)d_in[2];
    const float* bih = (const float*)d_in[3];
    const float* bhh = (const float*)d_in[4];
    const float* Wfc = (const float*)d_in[5];
    const float* bfc = (const float*)d_in[6];
    float* out = (float*)d_out;

    cudaFuncSetAttribute(gemm_xg_kernel, cudaFuncAttributeMaxDynamicSharedMemorySize, GEMM_SMEM);
    cudaFuncSetAttribute(gru_rec_kernel, cudaFuncAttributeMaxDynamicSharedMemorySize, REC_SMEM);

    dim3 ggrid(12, T_LEN);

    // layer 0
    gemm_xg_kernel<<<ggrid, 256, GEMM_SMEM>>>(x, Wih, bih, 0);
    gru_rec_kernel<<<128, 384, REC_SMEM>>>(Whh, bhh, 0);
    // layer 1
    gemm_xg_kernel<<<ggrid, 256, GEMM_SMEM>>>(nullptr, Wih + (size_t)G3 * H_N, bih + G3, 1);
    gru_rec_kernel<<<128, 384, REC_SMEM>>>(Whh + (size_t)G3 * H_N, bhh + G3, 1);
    // head
    fc_kernel<<<B_N, H_N>>>(Wfc, bfc, out);
}

// round 6
// speedup vs baseline: 1.2921x; 1.2921x over previous
#include <cuda_runtime.h>
#include <cuda_bf16.h>
#include <cstdint>

#define T_LEN 1024
#define B_N   128
#define H_N   256
#define G3    768

typedef unsigned long long u64;

// ---------------- scratch (device globals; no allocations allowed) ----------
__device__ float g_xg[(size_t)T_LEN * B_N * G3];      // [t][b][768]
__device__ float g_seq[(size_t)B_N * T_LEN * H_N];    // [b][t][256] layer-1 output
__device__ float g_hlast[B_N * H_N];                  // layer-2 final hidden

// ---------------- helpers ---------------------------------------------------
__device__ __forceinline__ float sigmoidf_(float x) {
    return __fdividef(1.0f, 1.0f + __expf(-x));
}
__device__ __forceinline__ float tanhf_(float x) {
    float ax = fabsf(x);
    float e  = __expf(-2.0f * ax);            // in (0,1], no overflow
    float t  = __fdividef(1.0f - e, 1.0f + e);
    return copysignf(t, x);
}

// packed fp32x2 FMA: d = a*b + d
__device__ __forceinline__ void fma2_(u64& d, u64 a, u64 b) {
    asm("fma.rn.f32x2 %0, %1, %2, %0;" : "+l"(d) : "l"(a), "l"(b));
}
__device__ __forceinline__ void unpack2_(u64 v, float& lo, float& hi) {
    asm("mov.b64 {%0, %1}, %2;" : "=f"(lo), "=f"(hi) : "l"(v));
}
__device__ __forceinline__ float foldadd_(u64 v) {
    float lo, hi; unpack2_(v, lo, hi); return lo + hi;
}

__device__ __forceinline__ void cluster_arrive_() {
    asm volatile("barrier.cluster.arrive.aligned;" ::: "memory");
}
__device__ __forceinline__ void cluster_wait_() {
    asm volatile("barrier.cluster.wait.aligned;" ::: "memory");
}
__device__ __forceinline__ void st_shared_cluster_f32(uint32_t laddr, uint32_t rank, float v) {
    uint32_t raddr;
    asm volatile("mapa.shared::cluster.u32 %0, %1, %2;" : "=r"(raddr) : "r"(laddr), "r"(rank));
    asm volatile("st.shared::cluster.f32 [%0], %1;" :: "r"(raddr), "f"(v) : "memory");
}
__device__ __forceinline__ uint32_t smem_u32(const void* p) {
    return (uint32_t)__cvta_generic_to_shared(p);
}

// ============================================================================
// Input projection GEMM (unchanged from R3 — measured at the scalar-FFMA floor)
// ============================================================================
#define SA_ST 258
#define SB_ST 258
#define GEMM_SMEM ((128*SA_ST + 64*SB_ST) * 4)

__global__ void __launch_bounds__(256, 1) gemm_xg_kernel(
    const float* __restrict__ Ax,
    const float* __restrict__ W,
    const float* __restrict__ bias,
    int use_gseq)
{
    extern __shared__ float sm[];
    float* sA = sm;                    // [128 m][258]
    float* sB = sm + 128 * SA_ST;      // [64  n][258]

    const float* A = use_gseq ? g_seq : Ax;

    const int tid = threadIdx.x;
    const int t  = blockIdx.y;
    const int nt = blockIdx.x;

#pragma unroll
    for (int i = 0; i < 32; i++) {
        int lin = i * 256 + tid;
        int m   = lin >> 6;
        int k4  = (lin & 63) << 2;
        float4 v = *(const float4*)(A + ((size_t)m * T_LEN + t) * H_N + k4);
        float* d = sA + m * SA_ST + k4;
        *(float2*)(d)     = make_float2(v.x, v.y);
        *(float2*)(d + 2) = make_float2(v.z, v.w);
    }
#pragma unroll
    for (int i = 0; i < 16; i++) {
        int lin = i * 256 + tid;
        int n   = lin >> 6;
        int k4  = (lin & 63) << 2;
        float4 v = *(const float4*)(W + ((size_t)(nt * 64 + n)) * H_N + k4);
        float* d = sB + n * SB_ST + k4;
        *(float2*)(d)     = make_float2(v.x, v.y);
        *(float2*)(d + 2) = make_float2(v.z, v.w);
    }
    __syncthreads();

    const int tx = tid >> 4;   // 0..15 -> n = tx + 16i
    const int ty = tid & 15;   // 0..15 -> m = ty + 16j

    u64 acc[8][4];
#pragma unroll
    for (int j = 0; j < 8; j++)
#pragma unroll
        for (int i = 0; i < 4; i++) acc[j][i] = 0ull;

#pragma unroll 4
    for (int kq = 0; kq < 128; kq++) {
        u64 a[8], b[4];
#pragma unroll
        for (int j = 0; j < 8; j++)
            a[j] = *(const u64*)(sA + (ty + (j << 4)) * SA_ST + 2 * kq);
#pragma unroll
        for (int i = 0; i < 4; i++)
            b[i] = *(const u64*)(sB + (tx + (i << 4)) * SB_ST + 2 * kq);
#pragma unroll
        for (int j = 0; j < 8; j++)
#pragma unroll
            for (int i = 0; i < 4; i++) fma2_(acc[j][i], a[j], b[i]);
    }

#pragma unroll
    for (int i = 0; i < 4; i++) {
        int n  = nt * 64 + tx + (i << 4);
        float bv = bias[n];
#pragma unroll
        for (int j = 0; j < 8; j++) {
            int m = ty + (j << 4);
            float lo, hi;
            unpack2_(acc[j][i], lo, hi);
            g_xg[((size_t)t * B_N + m) * G3 + n] = lo + hi + bv;
        }
    }
}

// ============================================================================
// GRU recurrence v5: 4-CTA clusters, 768 threads (6 warps/SMSP).
// Thread = (row 0..191, kh 0..1, bh 0..1):
//   warp layout: row = wrp*8 + (ln&7), kh = (ln>>3)&1, bh = ln>>4.
// All weights SMEM-resident: sW[row][260]: kh half at offset kh*130.
//   Bank map for a warp's 16 distinct (row,kh) u64 loads:
//   (row*260 + kh*130) mod 32 = 4*(row&7) + 2*kh -> 16 disjoint bank-pairs.
// Each thread: 1 row x 2 batches {2bh,2bh+1} x 128 k. Partials staged in sP
// (double-buffered), reduced over kh by elementwise threads (tid<256).
// ============================================================================
#define WROW_ST 260
#define KH_OFF  130
#define SP_ROW  10            // floats per row per phase (8 + pad 2, 8B-aligned)
#define REC_SMEM ((192*WROW_ST + 2*1024 + 2*192*SP_ROW) * 4)

__global__ void __cluster_dims__(4, 1, 1) __launch_bounds__(768, 1)
gru_rec_kernel(const float* __restrict__ Whh,   // this layer's [768][256]
               const float* __restrict__ bhh,   // this layer's [768]
               int layer)
{
    extern __shared__ float sm[];
    float* sW = sm;                              // [192][260]
    float* sH = sm + 192 * WROW_ST;              // [2][4 b][256]
    float* sP = sH + 2 * 1024;                   // [2][192][SP_ROW]

    const int tid  = threadIdx.x;               // 0..767
    const int rank = blockIdx.x & 3;
    const int b0   = (blockIdx.x >> 2) * 4;

    const int wrp = tid >> 5;                   // 0..23
    const int ln  = tid & 31;
    const int row = wrp * 8 + (ln & 7);         // 0..191
    const int kh  = (ln >> 3) & 1;              // k half
    const int bh  = ln >> 4;                    // batch half

    // ---- load weight slice: sW[row][kh*130 + j], j = k&127 ----
    for (int idx = tid; idx < 192 * 256; idx += 768) {
        int r  = idx >> 8;
        int k  = idx & 255;
        int rg = ((r >> 6) << 8) + (rank << 6) + (r & 63);
        sW[r * WROW_ST + (k >> 7) * KH_OFF + (k & 127)] = Whh[(size_t)rg * H_N + k];
    }
    // ---- zero h double buffer ----
    for (int i = tid; i < 2048; i += 768) sH[i] = 0.0f;

    // elementwise assignment (first 256 threads): one (u, b) each
    const int eu  = tid >> 2;                   // 0..63 (valid tid<256)
    const int eb  = tid & 3;
    const int eug = (rank << 6) + (eu & 63);
    float br_ = 0.f, bz_ = 0.f, bn_ = 0.f;
    if (tid < 256) {
        br_ = bhh[eug]; bz_ = bhh[256 + eug]; bn_ = bhh[512 + eug];
    }

    __syncthreads();
    cluster_arrive_();
    cluster_wait_();

    const float* wrow = sW + row * WROW_ST + kh * KH_OFF;

    int p = 0;
    for (int t = 0; t < T_LEN; t++) {
        // ---- issue xg LDGs before the wait (latency hides in barrier skew) --
        float xr = 0.f, xz = 0.f, xn = 0.f;
        if (tid < 256) {
            size_t xb = ((size_t)t * B_N + b0 + eb) * G3 + eug;
            xr = g_xg[xb]; xz = g_xg[xb + 256]; xn = g_xg[xb + 512];
        }
        if (t > 0) cluster_wait_();             // h[p] published by all peers

        // ---- FMA phase: 1 row x 2 batches x 128 k ----
        const float* hA = sH + p * 1024 + (2 * bh) * 256 + kh * 128;
        const float* hB = hA + 256;
        u64 acc0 = 0ull, acc1 = 0ull;
#pragma unroll
        for (int q = 0; q < 16; q++) {
            u64 w0 = *(const u64*)(wrow + 8 * q);
            u64 w1 = *(const u64*)(wrow + 8 * q + 2);
            u64 w2 = *(const u64*)(wrow + 8 * q + 4);
            u64 w3 = *(const u64*)(wrow + 8 * q + 6);
            ulonglong2 a0 = *(const ulonglong2*)(hA + 8 * q);
            ulonglong2 a1 = *(const ulonglong2*)(hA + 8 * q + 4);
            fma2_(acc0, w0, a0.x); fma2_(acc0, w1, a0.y);
            fma2_(acc0, w2, a1.x); fma2_(acc0, w3, a1.y);
            ulonglong2 c0 = *(const ulonglong2*)(hB + 8 * q);
            ulonglong2 c1 = *(const ulonglong2*)(hB + 8 * q + 4);
            fma2_(acc1, w0, c0.x); fma2_(acc1, w1, c0.y);
            fma2_(acc1, w2, c1.x); fma2_(acc1, w3, c1.y);
        }

        // ---- stage partials: sP[p][row][kh*4 + b] (float2 per thread) ----
        {
            float2 v = make_float2(foldadd_(acc0), foldadd_(acc1));
            *(float2*)(sP + (p * 192 + row) * SP_ROW + kh * 4 + 2 * bh) = v;
        }
        __syncthreads();

        // ---- reduce over kh + elementwise (first 256 threads) ----
        float hnew = 0.f;
        if (tid < 256) {
            const float* pb = sP + p * 192 * SP_ROW;
            float hr = pb[(      eu) * SP_ROW + eb] + pb[(      eu) * SP_ROW + 4 + eb] + br_;
            float hz = pb[( 64 + eu) * SP_ROW + eb] + pb[( 64 + eu) * SP_ROW + 4 + eb] + bz_;
            float hn = pb[(128 + eu) * SP_ROW + eb] + pb[(128 + eu) * SP_ROW + 4 + eb] + bn_;

            float hold = sH[p * 1024 + eb * 256 + eug];
            float r = sigmoidf_(xr + hr);
            float z = sigmoidf_(xz + hz);
            float n = tanhf_(xn + r * hn);
            hnew = (1.0f - z) * n + z * hold;

            // broadcast to all 4 cluster CTAs (incl. self)
            uint32_t la = smem_u32(sH + (1 - p) * 1024 + eb * 256 + eug);
#pragma unroll
            for (uint32_t rr = 0; rr < 4; rr++)
                st_shared_cluster_f32(la, rr, hnew);
        }

        cluster_arrive_();   // release: publishes DSMEM h stores + frees sH[p]/sP[p]

        // global stores off the critical path
        if (tid < 256) {
            if (layer == 0) {
                g_seq[((size_t)(b0 + eb) * T_LEN + t) * H_N + eug] = hnew;
            } else if (t == T_LEN - 1) {
                g_hlast[(b0 + eb) * H_N + eug] = hnew;
            }
        }
        p ^= 1;
    }
    cluster_wait_();   // don't exit while peers' DSMEM stores may be in flight
}

// ============================================================================
// Final FC: out[b][n] = sigmoid(dot(g_hlast[b], W_fc[n]) + b_fc[n])
// ============================================================================
__global__ void fc_kernel(const float* __restrict__ Wfc,
                          const float* __restrict__ bfc,
                          float* __restrict__ out)
{
    __shared__ float sh[H_N];
    const int b = blockIdx.x, n = threadIdx.x;
    sh[n] = g_hlast[b * H_N + n];
    __syncthreads();
    const float* w = Wfc + (size_t)n * H_N;
    float acc = 0.0f;
#pragma unroll 4
    for (int k = 0; k < H_N; k++) acc += sh[k] * w[k];
    out[b * H_N + n] = sigmoidf_(acc + bfc[n]);
}

// ============================================================================
extern "C" void kernel_launch(void* const* d_in, const int* in_sizes, int n_in,
                              void* d_out, int out_size)
{
    const float* x   = (const float*)d_in[0];
    const float* Wih = (const float*)d_in[1];
    const float* Whh = (const float*)d_in[2];
    const float* bih = (const float*)d_in[3];
    const float* bhh = (const float*)d_in[4];
    const float* Wfc = (const float*)d_in[5];
    const float* bfc = (const float*)d_in[6];
    float* out = (float*)d_out;

    cudaFuncSetAttribute(gemm_xg_kernel, cudaFuncAttributeMaxDynamicSharedMemorySize, GEMM_SMEM);
    cudaFuncSetAttribute(gru_rec_kernel, cudaFuncAttributeMaxDynamicSharedMemorySize, REC_SMEM);

    dim3 ggrid(12, T_LEN);

    // layer 0
    gemm_xg_kernel<<<ggrid, 256, GEMM_SMEM>>>(x, Wih, bih, 0);
    gru_rec_kernel<<<128, 768, REC_SMEM>>>(Whh, bhh, 0);
    // layer 1
    gemm_xg_kernel<<<ggrid, 256, GEMM_SMEM>>>(nullptr, Wih + (size_t)G3 * H_N, bih + G3, 1);
    gru_rec_kernel<<<128, 768, REC_SMEM>>>(Whh + (size_t)G3 * H_N, bhh + G3, 1);
    // head
    fc_kernel<<<B_N, H_N>>>(Wfc, bfc, out);
}

// round 8
// speedup vs baseline: 2.6332x; 2.0379x over previous
#include <cuda_runtime.h>
#include <cuda_bf16.h>
#include <cstdint>

#define T_LEN 1024
#define B_N   128
#define H_N   256
#define G3    768

typedef unsigned long long u64;

// ---------------- scratch (device globals; no allocations allowed) ----------
__device__ float g_xg[(size_t)T_LEN * B_N * G3];      // [t][b][768]
__device__ float g_seq[(size_t)B_N * T_LEN * H_N];    // [b][t][256] layer-1 output
__device__ float g_hlast[B_N * H_N];                  // layer-2 final hidden

// ---------------- helpers ---------------------------------------------------
__device__ __forceinline__ float sigmoidf_(float x) {
    return __fdividef(1.0f, 1.0f + __expf(-x));
}
__device__ __forceinline__ float tanhf_(float x) {
    float ax = fabsf(x);
    float e  = __expf(-2.0f * ax);
    float t  = __fdividef(1.0f - e, 1.0f + e);
    return copysignf(t, x);
}
__device__ __forceinline__ void fma2_(u64& d, u64 a, u64 b) {
    asm("fma.rn.f32x2 %0, %1, %2, %0;" : "+l"(d) : "l"(a), "l"(b));
}
__device__ __forceinline__ void unpack2_(u64 v, float& lo, float& hi) {
    asm("mov.b64 {%0, %1}, %2;" : "=f"(lo), "=f"(hi) : "l"(v));
}
__device__ __forceinline__ void cluster_arrive_() {
    asm volatile("barrier.cluster.arrive.aligned;" ::: "memory");
}
__device__ __forceinline__ void cluster_wait_() {
    asm volatile("barrier.cluster.wait.aligned;" ::: "memory");
}
__device__ __forceinline__ void st_shared_cluster_f32(uint32_t laddr, uint32_t rank, float v) {
    uint32_t raddr;
    asm volatile("mapa.shared::cluster.u32 %0, %1, %2;" : "=r"(raddr) : "r"(laddr), "r"(rank));
    asm volatile("st.shared::cluster.f32 [%0], %1;" :: "r"(raddr), "f"(v) : "memory");
}
__device__ __forceinline__ uint32_t smem_u32(const void* p) {
    return (uint32_t)__cvta_generic_to_shared(p);
}

// ---- mma.sync / ldmatrix wrappers (plain sm_80-era PTX; valid on sm_100) ----
__device__ __forceinline__ void ldmx4_(uint32_t* r, uint32_t addr) {
    asm volatile("ldmatrix.sync.aligned.m8n8.x4.shared.b16 {%0,%1,%2,%3}, [%4];"
                 : "=r"(r[0]), "=r"(r[1]), "=r"(r[2]), "=r"(r[3]) : "r"(addr));
}
__device__ __forceinline__ void ldmx2_(uint32_t* r, uint32_t addr) {
    asm volatile("ldmatrix.sync.aligned.m8n8.x2.shared.b16 {%0,%1}, [%2];"
                 : "=r"(r[0]), "=r"(r[1]) : "r"(addr));
}
__device__ __forceinline__ void mma16816_(float* c, const uint32_t* a, const uint32_t* b) {
    asm volatile(
        "mma.sync.aligned.m16n8k16.row.col.f32.bf16.bf16.f32 "
        "{%0,%1,%2,%3}, {%4,%5,%6,%7}, {%8,%9}, {%0,%1,%2,%3};"
        : "+f"(c[0]), "+f"(c[1]), "+f"(c[2]), "+f"(c[3])
        : "r"(a[0]), "r"(a[1]), "r"(a[2]), "r"(a[3]), "r"(b[0]), "r"(b[1]));
}

// ============================================================================
// Tensor-core input GEMM via mma.sync, 3-pass bf16 split:
//   D = Ahi*Bhi + Ahi*Blo + Alo*Bhi   (lo*lo term ~4e-6 rel, dropped)
// CTA = (nt 0..11, t 0..1023): M=128 (batch), N=64, K=256.
// fp32 -> bf16 hi/lo conversion INLINE during tile load.
// 256 threads / 8 warps; warp w owns m-tile rows [16w,16w+16) x all 64 n.
// smem tiles bf16, row stride 264 (ldmatrix conflict-free).
// ============================================================================
#define GT_ST   264
#define OFF_BIAS 0
#define OFF_AHI  256
#define OFF_ALO  (OFF_AHI + 128 * GT_ST * 2)
#define OFF_BHI  (OFF_ALO + 128 * GT_ST * 2)
#define OFF_BLO  (OFF_BHI + 64 * GT_ST * 2)
#define GT_SMEM  (OFF_BLO + 64 * GT_ST * 2)

__global__ void __launch_bounds__(256, 1) gemm_mma_kernel(
    const float* __restrict__ Ax,     // x (use_gseq==0) else g_seq
    const float* __restrict__ W,      // this layer's W_ih [768][256]
    const float* __restrict__ bias,   // this layer's b_ih [768]
    int use_gseq)
{
    extern __shared__ char smc[];
    const uint32_t sb = smem_u32(smc);
    float* sBias = (float*)(smc + OFF_BIAS);
    __nv_bfloat16* sAhi = (__nv_bfloat16*)(smc + OFF_AHI);
    __nv_bfloat16* sAlo = (__nv_bfloat16*)(smc + OFF_ALO);
    __nv_bfloat16* sBhi = (__nv_bfloat16*)(smc + OFF_BHI);
    __nv_bfloat16* sBlo = (__nv_bfloat16*)(smc + OFF_BLO);

    const float* A = use_gseq ? g_seq : Ax;

    const int tid = threadIdx.x;
    const int nt = blockIdx.x;        // 0..11
    const int t  = blockIdx.y;        // 0..1023

    if (tid < 64) sBias[tid] = bias[nt * 64 + tid];

    // ---- load + split A tile: 128 rows x 256 k (8192 float4 chunks) ----
#pragma unroll
    for (int i = 0; i < 32; i++) {
        int ch  = i * 256 + tid;
        int row = ch >> 6;
        int c4  = (ch & 63) << 2;
        float4 v = *(const float4*)(A + ((size_t)row * T_LEN + t) * H_N + c4);
        __nv_bfloat16 h0 = __float2bfloat16_rn(v.x);
        __nv_bfloat16 h1 = __float2bfloat16_rn(v.y);
        __nv_bfloat16 h2 = __float2bfloat16_rn(v.z);
        __nv_bfloat16 h3 = __float2bfloat16_rn(v.w);
        __nv_bfloat16 l0 = __float2bfloat16_rn(v.x - __bfloat162float(h0));
        __nv_bfloat16 l1 = __float2bfloat16_rn(v.y - __bfloat162float(h1));
        __nv_bfloat16 l2 = __float2bfloat16_rn(v.z - __bfloat162float(h2));
        __nv_bfloat16 l3 = __float2bfloat16_rn(v.w - __bfloat162float(h3));
        int o = row * GT_ST + c4;
        *(__nv_bfloat162*)(sAhi + o)     = __nv_bfloat162(h0, h1);
        *(__nv_bfloat162*)(sAhi + o + 2) = __nv_bfloat162(h2, h3);
        *(__nv_bfloat162*)(sAlo + o)     = __nv_bfloat162(l0, l1);
        *(__nv_bfloat162*)(sAlo + o + 2) = __nv_bfloat162(l2, l3);
    }
    // ---- load + split B tile: 64 W rows x 256 k (4096 float4 chunks) ----
#pragma unroll
    for (int i = 0; i < 16; i++) {
        int ch  = i * 256 + tid;
        int row = ch >> 6;
        int c4  = (ch & 63) << 2;
        float4 v = *(const float4*)(W + ((size_t)(nt * 64 + row)) * H_N + c4);
        __nv_bfloat16 h0 = __float2bfloat16_rn(v.x);
        __nv_bfloat16 h1 = __float2bfloat16_rn(v.y);
        __nv_bfloat16 h2 = __float2bfloat16_rn(v.z);
        __nv_bfloat16 h3 = __float2bfloat16_rn(v.w);
        __nv_bfloat16 l0 = __float2bfloat16_rn(v.x - __bfloat162float(h0));
        __nv_bfloat16 l1 = __float2bfloat16_rn(v.y - __bfloat162float(h1));
        __nv_bfloat16 l2 = __float2bfloat16_rn(v.z - __bfloat162float(h2));
        __nv_bfloat16 l3 = __float2bfloat16_rn(v.w - __bfloat162float(h3));
        int o = row * GT_ST + c4;
        *(__nv_bfloat162*)(sBhi + o)     = __nv_bfloat162(h0, h1);
        *(__nv_bfloat162*)(sBhi + o + 2) = __nv_bfloat162(h2, h3);
        *(__nv_bfloat162*)(sBlo + o)     = __nv_bfloat162(l0, l1);
        *(__nv_bfloat162*)(sBlo + o + 2) = __nv_bfloat162(l2, l3);
    }
    __syncthreads();

    const int wid = tid >> 5;
    const int l   = tid & 31;
    const int m0  = wid << 4;

    // ldmatrix lane addresses
    //   A x4: row = m0 + (l&15), col = (l>>4)*8   (+ 16*ks per k-step)
    //   B x2: row = (l&7),       col = ((l>>3)&1)*8  (lanes 16+ unused)
    const uint32_t aHi = sb + OFF_AHI + ((m0 + (l & 15)) * GT_ST + ((l >> 4) << 3)) * 2;
    const uint32_t aLo = sb + OFF_ALO + ((m0 + (l & 15)) * GT_ST + ((l >> 4) << 3)) * 2;
    const uint32_t bHi = sb + OFF_BHI + (((l & 7)) * GT_ST + (((l >> 3) & 1) << 3)) * 2;
    const uint32_t bLo = sb + OFF_BLO + (((l & 7)) * GT_ST + (((l >> 3) & 1) << 3)) * 2;

    float acc[8][4];
#pragma unroll
    for (int j = 0; j < 8; j++)
#pragma unroll
        for (int i = 0; i < 4; i++) acc[j][i] = 0.0f;

#pragma unroll 2
    for (int ks = 0; ks < 16; ks++) {
        uint32_t ah[4], al[4];
        ldmx4_(ah, aHi + ks * 32);
        ldmx4_(al, aLo + ks * 32);
#pragma unroll
        for (int j = 0; j < 8; j++) {
            uint32_t bh[2], bl[2];
            ldmx2_(bh, bHi + j * (8 * GT_ST * 2) + ks * 32);
            ldmx2_(bl, bLo + j * (8 * GT_ST * 2) + ks * 32);
            mma16816_(acc[j], ah, bh);
            mma16816_(acc[j], ah, bl);
            mma16816_(acc[j], al, bh);
        }
    }

    // ---- epilogue: d-frag -> g_xg[t][b][768] + bias ----
    {
        const int gp = l >> 2;         // 0..7
        const int tg = l & 3;          // 0..3
        float* dst0 = g_xg + ((size_t)t * B_N + m0 + gp) * G3 + nt * 64;
        float* dst1 = dst0 + 8 * G3;   // rows +8
#pragma unroll
        for (int j = 0; j < 8; j++) {
            int c = j * 8 + 2 * tg;
            float b0 = sBias[c], b1 = sBias[c + 1];
            *(float2*)(dst0 + c) = make_float2(acc[j][0] + b0, acc[j][1] + b1);
            *(float2*)(dst1 + c) = make_float2(acc[j][2] + b0, acc[j][3] + b1);
        }
    }
}

// ============================================================================
// GRU recurrence (v3, best measured): 4-CTA clusters, 384 threads.
// ============================================================================
#define WROW_ST 130
#define KH_OFF  66
#define SP_U64_ROW 9
#define REC_SMEM ((192*WROW_ST + 2*1024 + 2*192*SP_U64_ROW) * 4)

__global__ void __cluster_dims__(4, 1, 1) __launch_bounds__(384, 1)
gru_rec_kernel(const float* __restrict__ Whh,
               const float* __restrict__ bhh,
               int layer)
{
    extern __shared__ float sm[];
    float* sW = sm;                              // [192][130]
    float* sH = sm + 192 * WROW_ST;              // [2][4 b][256]
    u64*   sP = (u64*)(sH + 2 * 1024);           // [192][2 kh][4 b]

    const int tid  = threadIdx.x;
    const int rank = blockIdx.x & 3;
    const int b0   = (blockIdx.x >> 2) * 4;

    const int wrp = tid >> 5;
    const int ln  = tid & 31;
    const int row = wrp * 16 + (ln & 15);
    const int kh  = ln >> 4;
    const int jg  = ((row >> 6) << 8) + (rank << 6) + (row & 63);

    u64 wreg[32];
    {
        const float* wp = Whh + (size_t)jg * H_N + kh * 128;
#pragma unroll
        for (int j = 0; j < 32; j++)
            wreg[j] = *(const u64*)(wp + 2 * j);
    }
    for (int idx = tid; idx < 192 * 128; idx += 384) {
        int r   = idx >> 7;
        int kl  = idx & 127;
        int khh = kl >> 6;
        int off = kl & 63;
        int rg  = ((r >> 6) << 8) + (rank << 6) + (r & 63);
        sW[r * WROW_ST + khh * KH_OFF + off] =
            Whh[(size_t)rg * H_N + khh * 128 + 64 + off];
    }
    for (int i = tid; i < 2048; i += 384) sH[i] = 0.0f;

    const int eu  = tid >> 2;
    const int eb  = tid & 3;
    const int eug = (rank << 6) + (eu & 63);
    float br_ = 0.f, bz_ = 0.f, bn_ = 0.f;
    if (tid < 256) {
        br_ = bhh[eug]; bz_ = bhh[256 + eug]; bn_ = bhh[512 + eug];
    }

    __syncthreads();
    cluster_arrive_();
    cluster_wait_();

    const float* wsm = sW + row * WROW_ST + kh * KH_OFF;

    int p = 0;
    for (int t = 0; t < T_LEN; t++) {
        float xr = 0.f, xz = 0.f, xn = 0.f;
        if (tid < 256) {
            size_t xb = ((size_t)t * B_N + b0 + eb) * G3 + eug;
            xr = g_xg[xb]; xz = g_xg[xb + 256]; xn = g_xg[xb + 512];
        }
        if (t > 0) cluster_wait_();

        const float* hb = sH + p * 1024 + kh * 128;
        u64 acc0 = 0ull, acc1 = 0ull, acc2 = 0ull, acc3 = 0ull;
#pragma unroll
        for (int q = 0; q < 16; q++) {
            u64 wA = wreg[2 * q];
            u64 wB = wreg[2 * q + 1];
            ulonglong2 h0 = *(const ulonglong2*)(hb + 4 * q);
            fma2_(acc0, wA, h0.x); fma2_(acc0, wB, h0.y);
            ulonglong2 h1 = *(const ulonglong2*)(hb + 256 + 4 * q);
            fma2_(acc1, wA, h1.x); fma2_(acc1, wB, h1.y);
            ulonglong2 h2 = *(const ulonglong2*)(hb + 512 + 4 * q);
            fma2_(acc2, wA, h2.x); fma2_(acc2, wB, h2.y);
            ulonglong2 h3 = *(const ulonglong2*)(hb + 768 + 4 * q);
            fma2_(acc3, wA, h3.x); fma2_(acc3, wB, h3.y);
        }
#pragma unroll
        for (int q = 0; q < 16; q++) {
            u64 wA = *(const u64*)(wsm + 4 * q);
            u64 wB = *(const u64*)(wsm + 4 * q + 2);
            ulonglong2 h0 = *(const ulonglong2*)(hb + 64 + 4 * q);
            fma2_(acc0, wA, h0.x); fma2_(acc0, wB, h0.y);
            ulonglong2 h1 = *(const ulonglong2*)(hb + 320 + 4 * q);
            fma2_(acc1, wA, h1.x); fma2_(acc1, wB, h1.y);
            ulonglong2 h2 = *(const ulonglong2*)(hb + 576 + 4 * q);
            fma2_(acc2, wA, h2.x); fma2_(acc2, wB, h2.y);
            ulonglong2 h3 = *(const ulonglong2*)(hb + 832 + 4 * q);
            fma2_(acc3, wA, h3.x); fma2_(acc3, wB, h3.y);
        }

        {
            u64* d = sP + row * SP_U64_ROW + kh * 4;
            d[0] = acc0; d[1] = acc1; d[2] = acc2; d[3] = acc3;
        }
        __syncthreads();

        float hnew = 0.f;
        if (tid < 256) {
            const float2* pf = (const float2*)sP;
            int ir  = eu * SP_U64_ROW + eb;
            int iz  = (64 + eu) * SP_U64_ROW + eb;
            int in_ = (128 + eu) * SP_U64_ROW + eb;
            float2 r0 = pf[ir],  r1 = pf[ir + 4];
            float2 z0 = pf[iz],  z1 = pf[iz + 4];
            float2 n0 = pf[in_], n1 = pf[in_ + 4];
            float hr = r0.x + r0.y + r1.x + r1.y + br_;
            float hz = z0.x + z0.y + z1.x + z1.y + bz_;
            float hn = n0.x + n0.y + n1.x + n1.y + bn_;

            float hold = sH[p * 1024 + eb * 256 + eug];
            float r = sigmoidf_(xr + hr);
            float z = sigmoidf_(xz + hz);
            float n = tanhf_(xn + r * hn);
            hnew = (1.0f - z) * n + z * hold;

            uint32_t la = smem_u32(sH + (1 - p) * 1024 + eb * 256 + eug);
#pragma unroll
            for (uint32_t rr = 0; rr < 4; rr++)
                st_shared_cluster_f32(la, rr, hnew);
        }

        cluster_arrive_();

        if (tid < 256) {
            if (layer == 0) {
                g_seq[((size_t)(b0 + eb) * T_LEN + t) * H_N + eug] = hnew;
            } else if (t == T_LEN - 1) {
                g_hlast[(b0 + eb) * H_N + eug] = hnew;
            }
        }
        p ^= 1;
    }
    cluster_wait_();
}

// ============================================================================
// Final FC
// ============================================================================
__global__ void fc_kernel(const float* __restrict__ Wfc,
                          const float* __restrict__ bfc,
                          float* __restrict__ out)
{
    __shared__ float sh[H_N];
    const int b = blockIdx.x, n = threadIdx.x;
    sh[n] = g_hlast[b * H_N + n];
    __syncthreads();
    const float* w = Wfc + (size_t)n * H_N;
    float acc = 0.0f;
#pragma unroll 4
    for (int k = 0; k < H_N; k++) acc += sh[k] * w[k];
    out[b * H_N + n] = sigmoidf_(acc + bfc[n]);
}

// ============================================================================
extern "C" void kernel_launch(void* const* d_in, const int* in_sizes, int n_in,
                              void* d_out, int out_size)
{
    const float* x   = (const float*)d_in[0];
    const float* Wih = (const float*)d_in[1];
    const float* Whh = (const float*)d_in[2];
    const float* bih = (const float*)d_in[3];
    const float* bhh = (const float*)d_in[4];
    const float* Wfc = (const float*)d_in[5];
    const float* bfc = (const float*)d_in[6];
    float* out = (float*)d_out;

    cudaFuncSetAttribute(gemm_mma_kernel, cudaFuncAttributeMaxDynamicSharedMemorySize, GT_SMEM);
    cudaFuncSetAttribute(gru_rec_kernel, cudaFuncAttributeMaxDynamicSharedMemorySize, REC_SMEM);

    dim3 ggrid(12, T_LEN);

    // layer 0
    gemm_mma_kernel<<<ggrid, 256, GT_SMEM>>>(x, Wih, bih, 0);
    gru_rec_kernel<<<128, 384, REC_SMEM>>>(Whh, bhh, 0);
    // layer 1
    gemm_mma_kernel<<<ggrid, 256, GT_SMEM>>>(nullptr, Wih + (size_t)G3 * H_N, bih + G3, 1);
    gru_rec_kernel<<<128, 384, REC_SMEM>>>(Whh + (size_t)G3 * H_N, bhh + G3, 1);
    // head
    fc_kernel<<<B_N, H_N>>>(Wfc, bfc, out);
}

// round 9
// speedup vs baseline: 3.7891x; 1.4390x over previous
#include <cuda_runtime.h>
#include <cuda_bf16.h>
#include <cstdint>

#define T_LEN 1024
#define B_N   128
#define H_N   256
#define G3    768

typedef unsigned long long u64;

// ---------------- scratch (device globals; no allocations allowed) ----------
__device__ float g_xg[(size_t)T_LEN * B_N * G3];      // [t][b][768]
__device__ float g_seq[(size_t)B_N * T_LEN * H_N];    // [b][t][256] layer-1 output
__device__ float g_hlast[B_N * H_N];                  // layer-2 final hidden

// ---------------- helpers ---------------------------------------------------
__device__ __forceinline__ float sigmoidf_(float x) {
    return __fdividef(1.0f, 1.0f + __expf(-x));
}
__device__ __forceinline__ float tanhf_(float x) {
    float ax = fabsf(x);
    float e  = __expf(-2.0f * ax);
    float t  = __fdividef(1.0f - e, 1.0f + e);
    return copysignf(t, x);
}
__device__ __forceinline__ void cluster_arrive_() {
    asm volatile("barrier.cluster.arrive.aligned;" ::: "memory");
}
__device__ __forceinline__ void cluster_wait_() {
    asm volatile("barrier.cluster.wait.aligned;" ::: "memory");
}
__device__ __forceinline__ void st_cluster_b16(uint32_t laddr, uint32_t rank, unsigned short v) {
    uint32_t raddr;
    asm volatile("mapa.shared::cluster.u32 %0, %1, %2;" : "=r"(raddr) : "r"(laddr), "r"(rank));
    asm volatile("st.shared::cluster.b16 [%0], %1;" :: "r"(raddr), "h"(v) : "memory");
}
__device__ __forceinline__ uint32_t smem_u32(const void* p) {
    return (uint32_t)__cvta_generic_to_shared(p);
}

// ---- mma.sync / ldmatrix wrappers (sm_80-era PTX; valid on sm_100) ----
__device__ __forceinline__ void ldmx4_(uint32_t* r, uint32_t addr) {
    asm volatile("ldmatrix.sync.aligned.m8n8.x4.shared.b16 {%0,%1,%2,%3}, [%4];"
                 : "=r"(r[0]), "=r"(r[1]), "=r"(r[2]), "=r"(r[3]) : "r"(addr));
}
__device__ __forceinline__ void ldmx2_(uint32_t* r, uint32_t addr) {
    asm volatile("ldmatrix.sync.aligned.m8n8.x2.shared.b16 {%0,%1}, [%2];"
                 : "=r"(r[0]), "=r"(r[1]) : "r"(addr));
}
__device__ __forceinline__ void mma16816_(float* c, const uint32_t* a, const uint32_t* b) {
    asm volatile(
        "mma.sync.aligned.m16n8k16.row.col.f32.bf16.bf16.f32 "
        "{%0,%1,%2,%3}, {%4,%5,%6,%7}, {%8,%9}, {%0,%1,%2,%3};"
        : "+f"(c[0]), "+f"(c[1]), "+f"(c[2]), "+f"(c[3])
        : "r"(a[0]), "r"(a[1]), "r"(a[2]), "r"(a[3]), "r"(b[0]), "r"(b[1]));
}

// ============================================================================
// Input projection GEMM via mma.sync (unchanged from R7 — measured good)
// ============================================================================
#define GT_ST   264
#define OFF_BIAS 0
#define OFF_AHI  256
#define OFF_ALO  (OFF_AHI + 128 * GT_ST * 2)
#define OFF_BHI  (OFF_ALO + 128 * GT_ST * 2)
#define OFF_BLO  (OFF_BHI + 64 * GT_ST * 2)
#define GT_SMEM  (OFF_BLO + 64 * GT_ST * 2)

__global__ void __launch_bounds__(256, 1) gemm_mma_kernel(
    const float* __restrict__ Ax,
    const float* __restrict__ W,
    const float* __restrict__ bias,
    int use_gseq)
{
    extern __shared__ char smc[];
    const uint32_t sb = smem_u32(smc);
    float* sBias = (float*)(smc + OFF_BIAS);
    __nv_bfloat16* sAhi = (__nv_bfloat16*)(smc + OFF_AHI);
    __nv_bfloat16* sAlo = (__nv_bfloat16*)(smc + OFF_ALO);
    __nv_bfloat16* sBhi = (__nv_bfloat16*)(smc + OFF_BHI);
    __nv_bfloat16* sBlo = (__nv_bfloat16*)(smc + OFF_BLO);

    const float* A = use_gseq ? g_seq : Ax;

    const int tid = threadIdx.x;
    const int nt = blockIdx.x;
    const int t  = blockIdx.y;

    if (tid < 64) sBias[tid] = bias[nt * 64 + tid];

#pragma unroll
    for (int i = 0; i < 32; i++) {
        int ch  = i * 256 + tid;
        int row = ch >> 6;
        int c4  = (ch & 63) << 2;
        float4 v = *(const float4*)(A + ((size_t)row * T_LEN + t) * H_N + c4);
        __nv_bfloat16 h0 = __float2bfloat16_rn(v.x);
        __nv_bfloat16 h1 = __float2bfloat16_rn(v.y);
        __nv_bfloat16 h2 = __float2bfloat16_rn(v.z);
        __nv_bfloat16 h3 = __float2bfloat16_rn(v.w);
        __nv_bfloat16 l0 = __float2bfloat16_rn(v.x - __bfloat162float(h0));
        __nv_bfloat16 l1 = __float2bfloat16_rn(v.y - __bfloat162float(h1));
        __nv_bfloat16 l2 = __float2bfloat16_rn(v.z - __bfloat162float(h2));
        __nv_bfloat16 l3 = __float2bfloat16_rn(v.w - __bfloat162float(h3));
        int o = row * GT_ST + c4;
        *(__nv_bfloat162*)(sAhi + o)     = __nv_bfloat162(h0, h1);
        *(__nv_bfloat162*)(sAhi + o + 2) = __nv_bfloat162(h2, h3);
        *(__nv_bfloat162*)(sAlo + o)     = __nv_bfloat162(l0, l1);
        *(__nv_bfloat162*)(sAlo + o + 2) = __nv_bfloat162(l2, l3);
    }
#pragma unroll
    for (int i = 0; i < 16; i++) {
        int ch  = i * 256 + tid;
        int row = ch >> 6;
        int c4  = (ch & 63) << 2;
        float4 v = *(const float4*)(W + ((size_t)(nt * 64 + row)) * H_N + c4);
        __nv_bfloat16 h0 = __float2bfloat16_rn(v.x);
        __nv_bfloat16 h1 = __float2bfloat16_rn(v.y);
        __nv_bfloat16 h2 = __float2bfloat16_rn(v.z);
        __nv_bfloat16 h3 = __float2bfloat16_rn(v.w);
        __nv_bfloat16 l0 = __float2bfloat16_rn(v.x - __bfloat162float(h0));
        __nv_bfloat16 l1 = __float2bfloat16_rn(v.y - __bfloat162float(h1));
        __nv_bfloat16 l2 = __float2bfloat16_rn(v.z - __bfloat162float(h2));
        __nv_bfloat16 l3 = __float2bfloat16_rn(v.w - __bfloat162float(h3));
        int o = row * GT_ST + c4;
        *(__nv_bfloat162*)(sBhi + o)     = __nv_bfloat162(h0, h1);
        *(__nv_bfloat162*)(sBhi + o + 2) = __nv_bfloat162(h2, h3);
        *(__nv_bfloat162*)(sBlo + o)     = __nv_bfloat162(l0, l1);
        *(__nv_bfloat162*)(sBlo + o + 2) = __nv_bfloat162(l2, l3);
    }
    __syncthreads();

    const int wid = tid >> 5;
    const int l   = tid & 31;
    const int m0  = wid << 4;

    const uint32_t aHi = sb + OFF_AHI + ((m0 + (l & 15)) * GT_ST + ((l >> 4) << 3)) * 2;
    const uint32_t aLo = sb + OFF_ALO + ((m0 + (l & 15)) * GT_ST + ((l >> 4) << 3)) * 2;
    const uint32_t bHi = sb + OFF_BHI + (((l & 7)) * GT_ST + (((l >> 3) & 1) << 3)) * 2;
    const uint32_t bLo = sb + OFF_BLO + (((l & 7)) * GT_ST + (((l >> 3) & 1) << 3)) * 2;

    float acc[8][4];
#pragma unroll
    for (int j = 0; j < 8; j++)
#pragma unroll
        for (int i = 0; i < 4; i++) acc[j][i] = 0.0f;

#pragma unroll 2
    for (int ks = 0; ks < 16; ks++) {
        uint32_t ah[4], al[4];
        ldmx4_(ah, aHi + ks * 32);
        ldmx4_(al, aLo + ks * 32);
#pragma unroll
        for (int j = 0; j < 8; j++) {
            uint32_t bh[2], bl[2];
            ldmx2_(bh, bHi + j * (8 * GT_ST * 2) + ks * 32);
            ldmx2_(bl, bLo + j * (8 * GT_ST * 2) + ks * 32);
            mma16816_(acc[j], ah, bh);
            mma16816_(acc[j], ah, bl);
            mma16816_(acc[j], al, bh);
        }
    }

    {
        const int gp = l >> 2;
        const int tg = l & 3;
        float* dst0 = g_xg + ((size_t)t * B_N + m0 + gp) * G3 + nt * 64;
        float* dst1 = dst0 + 8 * G3;
#pragma unroll
        for (int j = 0; j < 8; j++) {
            int c = j * 8 + 2 * tg;
            float b0 = sBias[c], b1 = sBias[c + 1];
            *(float2*)(dst0 + c) = make_float2(acc[j][0] + b0, acc[j][1] + b1);
            *(float2*)(dst1 + c) = make_float2(acc[j][2] + b0, acc[j][3] + b1);
        }
    }
}

// ============================================================================
// GRU recurrence v6 (tensor-core): 4-CTA clusters, 192 threads (6 warps).
// hg = Whi*hhi + Whi*hlo + Wlo*hhi via mma.sync m16n8k16 (N=8, 4 real batches).
// Whi frags in REGISTERS (ldmatrix once at init). Wlo in SMEM (ldmatrix/step).
// h broadcast as bf16 hi/lo via st.shared::cluster.b16 from elementwise
// owners; h_old kept in owner registers. D-frags staged to sHG for the
// gate-triple gather; one __syncthreads + split cluster barrier per step.
// ============================================================================
#define R_ST      264
#define ROFF_ALO  0
#define ROFF_BHI  (192 * R_ST * 2)                  // [2 phases][8][264] bf16
#define ROFF_BLO  (ROFF_BHI + 2 * 8 * R_ST * 2)
#define ROFF_HG   (ROFF_BLO + 2 * 8 * R_ST * 2)     // [192][8] fp32
#define REC_SMEM  (ROFF_HG + 192 * 8 * 4)
#define B_PHASE   (8 * R_ST * 2)

__global__ void __cluster_dims__(4, 1, 1) __launch_bounds__(192, 1)
gru_rec_tc_kernel(const float* __restrict__ Whh,   // this layer's [768][256]
                  const float* __restrict__ bhh,   // this layer's [768]
                  int layer)
{
    extern __shared__ char smc[];
    const uint32_t sb = smem_u32(smc);
    __nv_bfloat16* sAlo = (__nv_bfloat16*)(smc + ROFF_ALO);
    float* sHG = (float*)(smc + ROFF_HG);

    const int tid  = threadIdx.x;               // 0..191
    const int rank = blockIdx.x & 3;
    const int b0   = (blockIdx.x >> 2) * 4;

    const int wid = tid >> 5;                   // 0..5
    const int l   = tid & 31;

    // ---- zero B buffers (both phases, hi+lo; covers batch-pad rows 4-7) ----
    for (int i = tid; i < (2 * B_PHASE + 2 * B_PHASE) / 4; i += 192)
        *(uint32_t*)(smc + ROFF_BHI + 4 * i) = 0u;

    // ---- fill sAlo with W_hi (bf16), ldmatrix A-hi frags to regs ----
    for (int idx = tid; idx < 192 * 128; idx += 192) {
        int row = idx >> 7;
        int kp  = idx & 127;
        int jg  = ((row >> 6) << 8) + (rank << 6) + (row & 63);
        float2 v = *(const float2*)(Whh + (size_t)jg * H_N + 2 * kp);
        __nv_bfloat162 hv(__float2bfloat16_rn(v.x), __float2bfloat16_rn(v.y));
        *(__nv_bfloat162*)(sAlo + row * R_ST + 2 * kp) = hv;
    }
    __syncthreads();

    uint32_t ahi[2][16][4];
#pragma unroll
    for (int m = 0; m < 2; m++) {
        int mt = 2 * wid + m;
        uint32_t base = sb + ROFF_ALO + (uint32_t)((16 * mt + (l & 15)) * R_ST + ((l >> 4) << 3)) * 2;
#pragma unroll
        for (int ks = 0; ks < 16; ks++)
            ldmx4_(ahi[m][ks], base + ks * 32);
    }
    __syncthreads();

    // ---- overwrite sAlo with W_lo ----
    for (int idx = tid; idx < 192 * 128; idx += 192) {
        int row = idx >> 7;
        int kp  = idx & 127;
        int jg  = ((row >> 6) << 8) + (rank << 6) + (row & 63);
        float2 v = *(const float2*)(Whh + (size_t)jg * H_N + 2 * kp);
        __nv_bfloat16 h0 = __float2bfloat16_rn(v.x);
        __nv_bfloat16 h1 = __float2bfloat16_rn(v.y);
        __nv_bfloat162 lv(__float2bfloat16_rn(v.x - __bfloat162float(h0)),
                          __float2bfloat16_rn(v.y - __bfloat162float(h1)));
        *(__nv_bfloat162*)(sAlo + row * R_ST + 2 * kp) = lv;
    }

    // ---- elementwise ownership: pair1 = tid (0..191), pair2 = 192+tid (tid<64)
    const int eu1 = tid >> 2,        eb1 = tid & 3;
    const int eu2 = (192 + tid) >> 2, eb2 = tid & 3;   // (192+tid)&3 == tid&3
    const int eug1 = (rank << 6) + eu1;
    const int eug2 = (rank << 6) + (eu2 & 63);
    const float br1 = bhh[eug1], bz1 = bhh[256 + eug1], bn1 = bhh[512 + eug1];
    float br2 = 0.f, bz2 = 0.f, bn2 = 0.f;
    if (tid < 64) { br2 = bhh[eug2]; bz2 = bhh[256 + eug2]; bn2 = bhh[512 + eug2]; }
    float hp1 = 0.0f, hp2 = 0.0f;

    // ldmatrix address bases (main loop)
    const uint32_t aloB0 = sb + ROFF_ALO + (uint32_t)((16 * (2 * wid)     + (l & 15)) * R_ST + ((l >> 4) << 3)) * 2;
    const uint32_t aloB1 = sb + ROFF_ALO + (uint32_t)((16 * (2 * wid + 1) + (l & 15)) * R_ST + ((l >> 4) << 3)) * 2;
    const uint32_t bOff  = (uint32_t)((l & 7) * R_ST + (((l >> 3) & 1) << 3)) * 2;

    __syncthreads();
    cluster_arrive_();
    cluster_wait_();

    int p = 0;
    for (int t = 0; t < T_LEN; t++) {
        // ---- xg prefetch (before wait: latency hides in barrier skew) ----
        float xr1, xz1, xn1, xr2 = 0.f, xz2 = 0.f, xn2 = 0.f;
        {
            size_t xb = ((size_t)t * B_N + b0 + eb1) * G3 + eug1;
            xr1 = g_xg[xb]; xz1 = g_xg[xb + 256]; xn1 = g_xg[xb + 512];
        }
        if (tid < 64) {
            size_t xb = ((size_t)t * B_N + b0 + eb2) * G3 + eug2;
            xr2 = g_xg[xb]; xz2 = g_xg[xb + 256]; xn2 = g_xg[xb + 512];
        }
        if (t > 0) cluster_wait_();

        // ---- MMA phase: 2 mtiles x 16 ksteps x 3 passes ----
        const uint32_t bHi = sb + ROFF_BHI + p * B_PHASE + bOff;
        const uint32_t bLo = sb + ROFF_BLO + p * B_PHASE + bOff;
        float c0[4] = {0.f, 0.f, 0.f, 0.f};
        float c1[4] = {0.f, 0.f, 0.f, 0.f};
#pragma unroll
        for (int ks = 0; ks < 16; ks++) {
            uint32_t bh[2], bl[2], al[4];
            ldmx2_(bh, bHi + ks * 32);
            ldmx2_(bl, bLo + ks * 32);
            ldmx4_(al, aloB0 + ks * 32);
            mma16816_(c0, ahi[0][ks], bh);
            mma16816_(c0, ahi[0][ks], bl);
            mma16816_(c0, al, bh);
            ldmx4_(al, aloB1 + ks * 32);
            mma16816_(c1, ahi[1][ks], bh);
            mma16816_(c1, ahi[1][ks], bl);
            mma16816_(c1, al, bh);
        }

        // ---- stage D frags -> sHG[row][8] ----
        {
            int r0 = 16 * (2 * wid) + (l >> 2);
            *(float2*)(sHG + r0 * 8 + 2 * (l & 3))       = make_float2(c0[0], c0[1]);
            *(float2*)(sHG + (r0 + 8) * 8 + 2 * (l & 3)) = make_float2(c0[2], c0[3]);
            int r1 = r0 + 16;
            *(float2*)(sHG + r1 * 8 + 2 * (l & 3))       = make_float2(c1[0], c1[1]);
            *(float2*)(sHG + (r1 + 8) * 8 + 2 * (l & 3)) = make_float2(c1[2], c1[3]);
        }
        __syncthreads();

        // ---- elementwise + bf16 hi/lo DSMEM broadcast ----
        const uint32_t bhiN = sb + ROFF_BHI + (1 - p) * B_PHASE;
        const uint32_t bloN = sb + ROFF_BLO + (1 - p) * B_PHASE;
        float hn1, hn2 = 0.f;
        {
            float hr = sHG[eu1 * 8 + eb1] + br1;
            float hz = sHG[(64 + eu1) * 8 + eb1] + bz1;
            float hn = sHG[(128 + eu1) * 8 + eb1] + bn1;
            float r = sigmoidf_(xr1 + hr);
            float z = sigmoidf_(xz1 + hz);
            float n = tanhf_(xn1 + r * hn);
            hn1 = (1.0f - z) * n + z * hp1;
            hp1 = hn1;
            __nv_bfloat16 hb = __float2bfloat16_rn(hn1);
            unsigned short hu = *(unsigned short*)&hb;
            __nv_bfloat16 lb = __float2bfloat16_rn(hn1 - __bfloat162float(hb));
            unsigned short lu = *(unsigned short*)&lb;
            uint32_t off = (uint32_t)(eb1 * R_ST + eug1) * 2;
#pragma unroll
            for (uint32_t rr = 0; rr < 4; rr++) {
                st_cluster_b16(bhiN + off, rr, hu);
                st_cluster_b16(bloN + off, rr, lu);
            }
        }
        if (tid < 64) {
            float hr = sHG[(eu2 & 63) * 8 + eb2] + br2;
            float hz = sHG[(64 + (eu2 & 63)) * 8 + eb2] + bz2;
            float hn = sHG[(128 + (eu2 & 63)) * 8 + eb2] + bn2;
            float r = sigmoidf_(xr2 + hr);
            float z = sigmoidf_(xz2 + hz);
            float n = tanhf_(xn2 + r * hn);
            hn2 = (1.0f - z) * n + z * hp2;
            hp2 = hn2;
            __nv_bfloat16 hb = __float2bfloat16_rn(hn2);
            unsigned short hu = *(unsigned short*)&hb;
            __nv_bfloat16 lb = __float2bfloat16_rn(hn2 - __bfloat162float(hb));
            unsigned short lu = *(unsigned short*)&lb;
            uint32_t off = (uint32_t)(eb2 * R_ST + eug2) * 2;
#pragma unroll
            for (uint32_t rr = 0; rr < 4; rr++) {
                st_cluster_b16(bhiN + off, rr, hu);
                st_cluster_b16(bloN + off, rr, lu);
            }
        }

        cluster_arrive_();   // release: publishes DSMEM bf16 h + frees sHG/sB[p]

        // global stores off the critical path
        if (layer == 0) {
            g_seq[((size_t)(b0 + eb1) * T_LEN + t) * H_N + eug1] = hn1;
            if (tid < 64)
                g_seq[((size_t)(b0 + eb2) * T_LEN + t) * H_N + eug2] = hn2;
        } else if (t == T_LEN - 1) {
            g_hlast[(b0 + eb1) * H_N + eug1] = hn1;
            if (tid < 64)
                g_hlast[(b0 + eb2) * H_N + eug2] = hn2;
        }
        p ^= 1;
    }
    cluster_wait_();
}

// ============================================================================
// Final FC
// ============================================================================
__global__ void fc_kernel(const float* __restrict__ Wfc,
                          const float* __restrict__ bfc,
                          float* __restrict__ out)
{
    __shared__ float sh[H_N];
    const int b = blockIdx.x, n = threadIdx.x;
    sh[n] = g_hlast[b * H_N + n];
    __syncthreads();
    const float* w = Wfc + (size_t)n * H_N;
    float acc = 0.0f;
#pragma unroll 4
    for (int k = 0; k < H_N; k++) acc += sh[k] * w[k];
    out[b * H_N + n] = sigmoidf_(acc + bfc[n]);
}

// ============================================================================
extern "C" void kernel_launch(void* const* d_in, const int* in_sizes, int n_in,
                              void* d_out, int out_size)
{
    const float* x   = (const float*)d_in[0];
    const float* Wih = (const float*)d_in[1];
    const float* Whh = (const float*)d_in[2];
    const float* bih = (const float*)d_in[3];
    const float* bhh = (const float*)d_in[4];
    const float* Wfc = (const float*)d_in[5];
    const float* bfc = (const float*)d_in[6];
    float* out = (float*)d_out;

    cudaFuncSetAttribute(gemm_mma_kernel, cudaFuncAttributeMaxDynamicSharedMemorySize, GT_SMEM);
    cudaFuncSetAttribute(gru_rec_tc_kernel, cudaFuncAttributeMaxDynamicSharedMemorySize, REC_SMEM);

    dim3 ggrid(12, T_LEN);

    // layer 0
    gemm_mma_kernel<<<ggrid, 256, GT_SMEM>>>(x, Wih, bih, 0);
    gru_rec_tc_kernel<<<128, 192, REC_SMEM>>>(Whh, bhh, 0);
    // layer 1
    gemm_mma_kernel<<<ggrid, 256, GT_SMEM>>>(nullptr, Wih + (size_t)G3 * H_N, bih + G3, 1);
    gru_rec_tc_kernel<<<128, 192, REC_SMEM>>>(Whh + (size_t)G3 * H_N, bhh + G3, 1);
    // head
    fc_kernel<<<B_N, H_N>>>(Wfc, bfc, out);
}

// round 10
// speedup vs baseline: 3.9518x; 1.0429x over previous
#include <cuda_runtime.h>
#include <cuda_bf16.h>
#include <cstdint>

#define T_LEN 1024
#define B_N   128
#define H_N   256
#define G3    768

typedef unsigned long long u64;

// ---------------- scratch (device globals; no allocations allowed) ----------
__device__ float g_xg[(size_t)T_LEN * B_N * G3];      // [t][b][768]
__device__ float g_seq[(size_t)B_N * T_LEN * H_N];    // [b][t][256] layer-1 output
__device__ float g_hlast[B_N * H_N];                  // layer-2 final hidden

// ---------------- helpers ---------------------------------------------------
__device__ __forceinline__ float sigmoidf_(float x) {
    return __fdividef(1.0f, 1.0f + __expf(-x));
}
__device__ __forceinline__ float tanhf_(float x) {
    float ax = fabsf(x);
    float e  = __expf(-2.0f * ax);
    float t  = __fdividef(1.0f - e, 1.0f + e);
    return copysignf(t, x);
}
__device__ __forceinline__ void cluster_arrive_() {
    asm volatile("barrier.cluster.arrive.aligned;" ::: "memory");
}
__device__ __forceinline__ void cluster_wait_() {
    asm volatile("barrier.cluster.wait.aligned;" ::: "memory");
}
__device__ __forceinline__ void st_cluster_b16(uint32_t laddr, uint32_t rank, unsigned short v) {
    uint32_t raddr;
    asm volatile("mapa.shared::cluster.u32 %0, %1, %2;" : "=r"(raddr) : "r"(laddr), "r"(rank));
    asm volatile("st.shared::cluster.b16 [%0], %1;" :: "r"(raddr), "h"(v) : "memory");
}
__device__ __forceinline__ uint32_t smem_u32(const void* p) {
    return (uint32_t)__cvta_generic_to_shared(p);
}

// ---- mma.sync / ldmatrix wrappers (sm_80-era PTX; valid on sm_100) ----
__device__ __forceinline__ void ldmx4_(uint32_t* r, uint32_t addr) {
    asm volatile("ldmatrix.sync.aligned.m8n8.x4.shared.b16 {%0,%1,%2,%3}, [%4];"
                 : "=r"(r[0]), "=r"(r[1]), "=r"(r[2]), "=r"(r[3]) : "r"(addr));
}
__device__ __forceinline__ void ldmx2_(uint32_t* r, uint32_t addr) {
    asm volatile("ldmatrix.sync.aligned.m8n8.x2.shared.b16 {%0,%1}, [%2];"
                 : "=r"(r[0]), "=r"(r[1]) : "r"(addr));
}
__device__ __forceinline__ void mma16816_(float* c, const uint32_t* a, const uint32_t* b) {
    asm volatile(
        "mma.sync.aligned.m16n8k16.row.col.f32.bf16.bf16.f32 "
        "{%0,%1,%2,%3}, {%4,%5,%6,%7}, {%8,%9}, {%0,%1,%2,%3};"
        : "+f"(c[0]), "+f"(c[1]), "+f"(c[2]), "+f"(c[3])
        : "r"(a[0]), "r"(a[1]), "r"(a[2]), "r"(a[3]), "r"(b[0]), "r"(b[1]));
}

// ============================================================================
// Input projection GEMM via mma.sync (unchanged — measured good)
// ============================================================================
#define GT_ST   264
#define OFF_BIAS 0
#define OFF_AHI  256
#define OFF_ALO  (OFF_AHI + 128 * GT_ST * 2)
#define OFF_BHI  (OFF_ALO + 128 * GT_ST * 2)
#define OFF_BLO  (OFF_BHI + 64 * GT_ST * 2)
#define GT_SMEM  (OFF_BLO + 64 * GT_ST * 2)

__global__ void __launch_bounds__(256, 1) gemm_mma_kernel(
    const float* __restrict__ Ax,
    const float* __restrict__ W,
    const float* __restrict__ bias,
    int use_gseq)
{
    extern __shared__ char smc[];
    const uint32_t sb = smem_u32(smc);
    float* sBias = (float*)(smc + OFF_BIAS);
    __nv_bfloat16* sAhi = (__nv_bfloat16*)(smc + OFF_AHI);
    __nv_bfloat16* sAlo = (__nv_bfloat16*)(smc + OFF_ALO);
    __nv_bfloat16* sBhi = (__nv_bfloat16*)(smc + OFF_BHI);
    __nv_bfloat16* sBlo = (__nv_bfloat16*)(smc + OFF_BLO);

    const float* A = use_gseq ? g_seq : Ax;

    const int tid = threadIdx.x;
    const int nt = blockIdx.x;
    const int t  = blockIdx.y;

    if (tid < 64) sBias[tid] = bias[nt * 64 + tid];

#pragma unroll
    for (int i = 0; i < 32; i++) {
        int ch  = i * 256 + tid;
        int row = ch >> 6;
        int c4  = (ch & 63) << 2;
        float4 v = *(const float4*)(A + ((size_t)row * T_LEN + t) * H_N + c4);
        __nv_bfloat16 h0 = __float2bfloat16_rn(v.x);
        __nv_bfloat16 h1 = __float2bfloat16_rn(v.y);
        __nv_bfloat16 h2 = __float2bfloat16_rn(v.z);
        __nv_bfloat16 h3 = __float2bfloat16_rn(v.w);
        __nv_bfloat16 l0 = __float2bfloat16_rn(v.x - __bfloat162float(h0));
        __nv_bfloat16 l1 = __float2bfloat16_rn(v.y - __bfloat162float(h1));
        __nv_bfloat16 l2 = __float2bfloat16_rn(v.z - __bfloat162float(h2));
        __nv_bfloat16 l3 = __float2bfloat16_rn(v.w - __bfloat162float(h3));
        int o = row * GT_ST + c4;
        *(__nv_bfloat162*)(sAhi + o)     = __nv_bfloat162(h0, h1);
        *(__nv_bfloat162*)(sAhi + o + 2) = __nv_bfloat162(h2, h3);
        *(__nv_bfloat162*)(sAlo + o)     = __nv_bfloat162(l0, l1);
        *(__nv_bfloat162*)(sAlo + o + 2) = __nv_bfloat162(l2, l3);
    }
#pragma unroll
    for (int i = 0; i < 16; i++) {
        int ch  = i * 256 + tid;
        int row = ch >> 6;
        int c4  = (ch & 63) << 2;
        float4 v = *(const float4*)(W + ((size_t)(nt * 64 + row)) * H_N + c4);
        __nv_bfloat16 h0 = __float2bfloat16_rn(v.x);
        __nv_bfloat16 h1 = __float2bfloat16_rn(v.y);
        __nv_bfloat16 h2 = __float2bfloat16_rn(v.z);
        __nv_bfloat16 h3 = __float2bfloat16_rn(v.w);
        __nv_bfloat16 l0 = __float2bfloat16_rn(v.x - __bfloat162float(h0));
        __nv_bfloat16 l1 = __float2bfloat16_rn(v.y - __bfloat162float(h1));
        __nv_bfloat16 l2 = __float2bfloat16_rn(v.z - __bfloat162float(h2));
        __nv_bfloat16 l3 = __float2bfloat16_rn(v.w - __bfloat162float(h3));
        int o = row * GT_ST + c4;
        *(__nv_bfloat162*)(sBhi + o)     = __nv_bfloat162(h0, h1);
        *(__nv_bfloat162*)(sBhi + o + 2) = __nv_bfloat162(h2, h3);
        *(__nv_bfloat162*)(sBlo + o)     = __nv_bfloat162(l0, l1);
        *(__nv_bfloat162*)(sBlo + o + 2) = __nv_bfloat162(l2, l3);
    }
    __syncthreads();

    const int wid = tid >> 5;
    const int l   = tid & 31;
    const int m0  = wid << 4;

    const uint32_t aHi = sb + OFF_AHI + ((m0 + (l & 15)) * GT_ST + ((l >> 4) << 3)) * 2;
    const uint32_t aLo = sb + OFF_ALO + ((m0 + (l & 15)) * GT_ST + ((l >> 4) << 3)) * 2;
    const uint32_t bHi = sb + OFF_BHI + (((l & 7)) * GT_ST + (((l >> 3) & 1) << 3)) * 2;
    const uint32_t bLo = sb + OFF_BLO + (((l & 7)) * GT_ST + (((l >> 3) & 1) << 3)) * 2;

    float acc[8][4];
#pragma unroll
    for (int j = 0; j < 8; j++)
#pragma unroll
        for (int i = 0; i < 4; i++) acc[j][i] = 0.0f;

#pragma unroll 2
    for (int ks = 0; ks < 16; ks++) {
        uint32_t ah[4], al[4];
        ldmx4_(ah, aHi + ks * 32);
        ldmx4_(al, aLo + ks * 32);
#pragma unroll
        for (int j = 0; j < 8; j++) {
            uint32_t bh[2], bl[2];
            ldmx2_(bh, bHi + j * (8 * GT_ST * 2) + ks * 32);
            ldmx2_(bl, bLo + j * (8 * GT_ST * 2) + ks * 32);
            mma16816_(acc[j], ah, bh);
            mma16816_(acc[j], ah, bl);
            mma16816_(acc[j], al, bh);
        }
    }

    {
        const int gp = l >> 2;
        const int tg = l & 3;
        float* dst0 = g_xg + ((size_t)t * B_N + m0 + gp) * G3 + nt * 64;
        float* dst1 = dst0 + 8 * G3;
#pragma unroll
        for (int j = 0; j < 8; j++) {
            int c = j * 8 + 2 * tg;
            float b0 = sBias[c], b1 = sBias[c + 1];
            *(float2*)(dst0 + c) = make_float2(acc[j][0] + b0, acc[j][1] + b1);
            *(float2*)(dst1 + c) = make_float2(acc[j][2] + b0, acc[j][3] + b1);
        }
    }
}

// ============================================================================
// GRU recurrence v7 (tensor-core): 4-CTA clusters, 384 threads / 12 warps.
// Warp w owns ONE 16-row m-tile (was 2) -> half the per-warp MMA chain,
// 3 warps/SMSP for latency hiding, ahi down to 64 regs/thread.
// Elementwise: single tranche (tid<256, one (unit,batch) each).
// Everything else identical to the measured v6 skeleton.
// ============================================================================
#define R_ST      264
#define ROFF_ALO  0
#define ROFF_BHI  (192 * R_ST * 2)                  // [2 phases][8][264] bf16
#define ROFF_BLO  (ROFF_BHI + 2 * 8 * R_ST * 2)
#define ROFF_HG   (ROFF_BLO + 2 * 8 * R_ST * 2)     // [192][8] fp32
#define REC_SMEM  (ROFF_HG + 192 * 8 * 4)
#define B_PHASE   (8 * R_ST * 2)

__global__ void __cluster_dims__(4, 1, 1) __launch_bounds__(384, 1)
gru_rec_tc_kernel(const float* __restrict__ Whh,   // this layer's [768][256]
                  const float* __restrict__ bhh,   // this layer's [768]
                  int layer)
{
    extern __shared__ char smc[];
    const uint32_t sb = smem_u32(smc);
    __nv_bfloat16* sAlo = (__nv_bfloat16*)(smc + ROFF_ALO);
    float* sHG = (float*)(smc + ROFF_HG);

    const int tid  = threadIdx.x;               // 0..383
    const int rank = blockIdx.x & 3;
    const int b0   = (blockIdx.x >> 2) * 4;

    const int wid = tid >> 5;                   // 0..11, m-tile index
    const int l   = tid & 31;

    // ---- zero B buffers (both phases, hi+lo; covers batch-pad rows 4-7) ----
    for (int i = tid; i < (4 * B_PHASE) / 4; i += 384)
        *(uint32_t*)(smc + ROFF_BHI + 4 * i) = 0u;

    // ---- fill sAlo with W_hi (bf16), ldmatrix A-hi frags to regs ----
    for (int idx = tid; idx < 192 * 128; idx += 384) {
        int row = idx >> 7;
        int kp  = idx & 127;
        int jg  = ((row >> 6) << 8) + (rank << 6) + (row & 63);
        float2 v = *(const float2*)(Whh + (size_t)jg * H_N + 2 * kp);
        __nv_bfloat162 hv(__float2bfloat16_rn(v.x), __float2bfloat16_rn(v.y));
        *(__nv_bfloat162*)(sAlo + row * R_ST + 2 * kp) = hv;
    }
    __syncthreads();

    uint32_t ahi[16][4];
    {
        uint32_t base = sb + ROFF_ALO + (uint32_t)((16 * wid + (l & 15)) * R_ST + ((l >> 4) << 3)) * 2;
#pragma unroll
        for (int ks = 0; ks < 16; ks++)
            ldmx4_(ahi[ks], base + ks * 32);
    }
    __syncthreads();

    // ---- overwrite sAlo with W_lo ----
    for (int idx = tid; idx < 192 * 128; idx += 384) {
        int row = idx >> 7;
        int kp  = idx & 127;
        int jg  = ((row >> 6) << 8) + (rank << 6) + (row & 63);
        float2 v = *(const float2*)(Whh + (size_t)jg * H_N + 2 * kp);
        __nv_bfloat16 h0 = __float2bfloat16_rn(v.x);
        __nv_bfloat16 h1 = __float2bfloat16_rn(v.y);
        __nv_bfloat162 lv(__float2bfloat16_rn(v.x - __bfloat162float(h0)),
                          __float2bfloat16_rn(v.y - __bfloat162float(h1)));
        *(__nv_bfloat162*)(sAlo + row * R_ST + 2 * kp) = lv;
    }

    // ---- elementwise ownership: tid<256, one (unit, batch) each ----
    const int eu  = tid >> 2;                   // 0..63 (valid tid<256)
    const int eb  = tid & 3;
    const int eug = (rank << 6) + (eu & 63);
    float br_ = 0.f, bz_ = 0.f, bn_ = 0.f;
    if (tid < 256) {
        br_ = bhh[eug]; bz_ = bhh[256 + eug]; bn_ = bhh[512 + eug];
    }
    float hprev = 0.0f;

    // ldmatrix address bases (main loop)
    const uint32_t aloB = sb + ROFF_ALO + (uint32_t)((16 * wid + (l & 15)) * R_ST + ((l >> 4) << 3)) * 2;
    const uint32_t bOff = (uint32_t)((l & 7) * R_ST + (((l >> 3) & 1) << 3)) * 2;

    __syncthreads();
    cluster_arrive_();
    cluster_wait_();

    int p = 0;
    for (int t = 0; t < T_LEN; t++) {
        // ---- xg prefetch (before wait: latency hides in barrier skew) ----
        float xr = 0.f, xz = 0.f, xn = 0.f;
        if (tid < 256) {
            size_t xb = ((size_t)t * B_N + b0 + eb) * G3 + eug;
            xr = g_xg[xb]; xz = g_xg[xb + 256]; xn = g_xg[xb + 512];
        }
        if (t > 0) cluster_wait_();

        // ---- MMA phase: 1 m-tile x 16 ksteps x 3 passes ----
        const uint32_t bHi = sb + ROFF_BHI + p * B_PHASE + bOff;
        const uint32_t bLo = sb + ROFF_BLO + p * B_PHASE + bOff;
        float c0[4] = {0.f, 0.f, 0.f, 0.f};
#pragma unroll
        for (int ks = 0; ks < 16; ks++) {
            uint32_t bh[2], bl[2], al[4];
            ldmx2_(bh, bHi + ks * 32);
            ldmx2_(bl, bLo + ks * 32);
            ldmx4_(al, aloB + ks * 32);
            mma16816_(c0, ahi[ks], bh);
            mma16816_(c0, ahi[ks], bl);
            mma16816_(c0, al, bh);
        }

        // ---- stage D frags -> sHG[row][8] ----
        {
            int r0 = 16 * wid + (l >> 2);
            *(float2*)(sHG + r0 * 8 + 2 * (l & 3))       = make_float2(c0[0], c0[1]);
            *(float2*)(sHG + (r0 + 8) * 8 + 2 * (l & 3)) = make_float2(c0[2], c0[3]);
        }
        __syncthreads();

        // ---- elementwise + bf16 hi/lo DSMEM broadcast (single tranche) ----
        float hnew = 0.f;
        if (tid < 256) {
            const uint32_t bhiN = sb + ROFF_BHI + (1 - p) * B_PHASE;
            const uint32_t bloN = sb + ROFF_BLO + (1 - p) * B_PHASE;
            float hr = sHG[eu * 8 + eb] + br_;
            float hz = sHG[(64 + eu) * 8 + eb] + bz_;
            float hn = sHG[(128 + eu) * 8 + eb] + bn_;
            float r = sigmoidf_(xr + hr);
            float z = sigmoidf_(xz + hz);
            float n = tanhf_(xn + r * hn);
            hnew = (1.0f - z) * n + z * hprev;
            hprev = hnew;
            __nv_bfloat16 hb = __float2bfloat16_rn(hnew);
            unsigned short hu = *(unsigned short*)&hb;
            __nv_bfloat16 lb = __float2bfloat16_rn(hnew - __bfloat162float(hb));
            unsigned short lu = *(unsigned short*)&lb;
            uint32_t off = (uint32_t)(eb * R_ST + eug) * 2;
#pragma unroll
            for (uint32_t rr = 0; rr < 4; rr++) {
                st_cluster_b16(bhiN + off, rr, hu);
                st_cluster_b16(bloN + off, rr, lu);
            }
        }

        cluster_arrive_();   // release: publishes DSMEM bf16 h + frees sHG/sB[p]

        // global stores off the critical path
        if (tid < 256) {
            if (layer == 0) {
                g_seq[((size_t)(b0 + eb) * T_LEN + t) * H_N + eug] = hnew;
            } else if (t == T_LEN - 1) {
                g_hlast[(b0 + eb) * H_N + eug] = hnew;
            }
        }
        p ^= 1;
    }
    cluster_wait_();
}

// ============================================================================
// Final FC
// ============================================================================
__global__ void fc_kernel(const float* __restrict__ Wfc,
                          const float* __restrict__ bfc,
                          float* __restrict__ out)
{
    __shared__ float sh[H_N];
    const int b = blockIdx.x, n = threadIdx.x;
    sh[n] = g_hlast[b * H_N + n];
    __syncthreads();
    const float* w = Wfc + (size_t)n * H_N;
    float acc = 0.0f;
#pragma unroll 4
    for (int k = 0; k < H_N; k++) acc += sh[k] * w[k];
    out[b * H_N + n] = sigmoidf_(acc + bfc[n]);
}

// ============================================================================
extern "C" void kernel_launch(void* const* d_in, const int* in_sizes, int n_in,
                              void* d_out, int out_size)
{
    const float* x   = (const float*)d_in[0];
    const float* Wih = (const float*)d_in[1];
    const float* Whh = (const float*)d_in[2];
    const float* bih = (const float*)d_in[3];
    const float* bhh = (const float*)d_in[4];
    const float* Wfc = (const float*)d_in[5];
    const float* bfc = (const float*)d_in[6];
    float* out = (float*)d_out;

    cudaFuncSetAttribute(gemm_mma_kernel, cudaFuncAttributeMaxDynamicSharedMemorySize, GT_SMEM);
    cudaFuncSetAttribute(gru_rec_tc_kernel, cudaFuncAttributeMaxDynamicSharedMemorySize, REC_SMEM);

    dim3 ggrid(12, T_LEN);

    // layer 0
    gemm_mma_kernel<<<ggrid, 256, GT_SMEM>>>(x, Wih, bih, 0);
    gru_rec_tc_kernel<<<128, 384, REC_SMEM>>>(Whh, bhh, 0);
    // layer 1
    gemm_mma_kernel<<<ggrid, 256, GT_SMEM>>>(nullptr, Wih + (size_t)G3 * H_N, bih + G3, 1);
    gru_rec_tc_kernel<<<128, 384, REC_SMEM>>>(Whh + (size_t)G3 * H_N, bhh + G3, 1);
    // head
    fc_kernel<<<B_N, H_N>>>(Wfc, bfc, out);
}